// round 15
// baseline (speedup 1.0000x reference)
#include <cuda_runtime.h>
#include <cuda_bf16.h>
#include <stdint.h>

#define NDIM 2048
#define CDIM 2048
#define HEADS 16
#define TSTEPS 10

#define NCHUNK 32
#define BKC    64
#define TILEB  16384             // one tile: 128 rows x 128 bytes (SW128, contiguous)
#define STAGEB (4 * TILEB)       // 2 A-splits + 2 B-splits = 64KB
#define NSTAGE 3
#define CTRLB  1024
#define SMEM_TOTAL (CTRLB + NSTAGE * STAGEB)   // 197632

// idesc kind::f16, bf16 x bf16 -> f32, M=128, N=64
#define IDESC 0x8100490u

// Flag window: any |y_err| < DELTA is either provably maskless or repaired
// exactly (sequential-order fp32). IF boundaries y=1/m are >= 1/90 apart.
#define DELTA 5e-4f
#define FLAG_CAP (1u << 22)

#if defined(__CUDA_ARCH__) && \
    (defined(__CUDA_ARCH_FEAT_SM103_ALL) || defined(__CUDA_ARCH_FEAT_SM100_ALL) || \
     defined(__CUDA_ARCH_SPECIFIC__))
#define TC_OK 1
#else
#define TC_OK 0
#endif

// ---------------------------------------------------------------------------
// Global scratch. Operand planes are stored TILED: plane = [rowblk 16][kchunk 32]
// of 16KB tiles, each tile SW128-swizzled exactly as the MMA smem layout.
// ---------------------------------------------------------------------------
__device__ __align__(256) unsigned short g_masks[6][NDIM * CDIM];      // 48 MB
__device__ __align__(256) __nv_bfloat16 g_as[2][2][NDIM * CDIM];       // 32 MB
__device__ __align__(256) __nv_bfloat16 g_ws[4][2][CDIM * CDIM];       // 64 MB
__device__ __align__(256) float g_wt[3][CDIM * CDIM];                  // 48 MB (repair)
__device__ __align__(256) __nv_bfloat16 g_xms[2][NDIM * CDIM];         // 16 MB
__device__ unsigned g_flagcnt;
__device__ unsigned g_flags[FLAG_CAP];                                 // 16 MB

// tiled element address (byte offset within a plane)
__device__ __forceinline__ size_t tiled_off(int row, int col) {
    const size_t tile = (size_t)(row >> 7) * 32 + (col >> 6);
    uint32_t inner = (uint32_t)(row & 127) * 128 + (col & 63) * 2;
    inner ^= (inner >> 3) & 0x70;            // SW128
    return tile * TILEB + inner;
}

// ---------------------------------------------------------------------------
__device__ __forceinline__ void split2(float a, __nv_bfloat16& h0, __nv_bfloat16& h1) {
    h0 = __float2bfloat16_rn(a);
    h1 = __float2bfloat16_rn(a - __bfloat162float(h0));
}

__device__ __forceinline__ unsigned if_scan_mask(float y) {
    float v = 0.f;
    unsigned m = 0;
#pragma unroll
    for (int t = 0; t < TSTEPS; ++t) {
        v += y;
        if (v >= 1.0f) { m |= (1u << t); v = 0.f; }
    }
    return m;
}

__device__ __forceinline__ unsigned mask_or_flag(float y, unsigned enc) {
    const unsigned mlo = if_scan_mask(y - DELTA);
    const unsigned mhi = if_scan_mask(y + DELTA);
    const bool flag = (mlo != mhi);
    const unsigned bal = __ballot_sync(0xFFFFFFFFu, flag);
    if (bal) {
        const int lane = threadIdx.x & 31;
        const int leader = __ffs(bal) - 1;
        unsigned base = 0;
        if (lane == leader) base = atomicAdd(&g_flagcnt, (unsigned)__popc(bal));
        base = __shfl_sync(0xFFFFFFFFu, base, leader);
        if (flag) {
            const unsigned off = (unsigned)__popc(bal & ((1u << lane) - 1u));
            if (base + off < FLAG_CAP) g_flags[base + off] = enc;
        }
    }
    return mlo;
}

#if TC_OK
// ---------------------------------------------------------------------------
// tcgen05 / bulk-copy PTX helpers (arch-specific pass only)
// ---------------------------------------------------------------------------
__device__ __forceinline__ uint32_t smem_u32(const void* p) {
    return (uint32_t)__cvta_generic_to_shared(p);
}
__device__ __forceinline__ uint64_t mkdesc(uint32_t addr) {
    return 0x4000404000010000ULL | (uint64_t)((addr >> 4) & 0x3FFF);
}
__device__ __forceinline__ void mma_ss(uint32_t d, uint64_t ad, uint64_t bd, uint32_t en) {
    asm volatile(
        "{\n\t.reg .pred p;\n\tsetp.ne.u32 p, %5, 0;\n\t"
        "tcgen05.mma.cta_group::1.kind::f16 [%0], %1, %2, %3, {%4, %4, %4, %4}, p;\n\t}"
        :: "r"(d), "l"(ad), "l"(bd), "r"(IDESC), "r"(0u), "r"(en) : "memory");
}
__device__ __forceinline__ void mbwait(uint32_t mb, int phase) {
    asm volatile(
        "{\n\t.reg .pred P;\n\tWL%=:\n\t"
        "mbarrier.try_wait.parity.acquire.cta.shared::cta.b64 P, [%0], %1, 0x989680;\n\t"
        "@P bra.uni WD%=;\n\tbra.uni WL%=;\n\tWD%=:\n\t}"
        :: "r"(mb), "r"(phase) : "memory");
}
// 1D bulk copy: 16KB contiguous GMEM -> SMEM, mbarrier complete_tx.
__device__ __forceinline__ void bulkcp(uint32_t dst, const void* src, uint32_t mbar) {
    asm volatile(
        "cp.async.bulk.shared::cluster.global.mbarrier::complete_tx::bytes "
        "[%0], [%1], %2, [%3];"
        :: "r"(dst), "l"(src), "r"((unsigned)TILEB), "r"(mbar) : "memory");
}
#define LDTM32(r, addr) \
    asm volatile( \
        "tcgen05.ld.sync.aligned.32x32b.x32.b32 " \
        "{%0, %1, %2, %3, %4, %5, %6, %7, " \
        " %8, %9, %10, %11, %12, %13, %14, %15, " \
        " %16, %17, %18, %19, %20, %21, %22, %23, " \
        " %24, %25, %26, %27, %28, %29, %30, %31}, [%32];" \
        : "=r"((r)[0]),  "=r"((r)[1]),  "=r"((r)[2]),  "=r"((r)[3]), \
          "=r"((r)[4]),  "=r"((r)[5]),  "=r"((r)[6]),  "=r"((r)[7]), \
          "=r"((r)[8]),  "=r"((r)[9]),  "=r"((r)[10]), "=r"((r)[11]), \
          "=r"((r)[12]), "=r"((r)[13]), "=r"((r)[14]), "=r"((r)[15]), \
          "=r"((r)[16]), "=r"((r)[17]), "=r"((r)[18]), "=r"((r)[19]), \
          "=r"((r)[20]), "=r"((r)[21]), "=r"((r)[22]), "=r"((r)[23]), \
          "=r"((r)[24]), "=r"((r)[25]), "=r"((r)[26]), "=r"((r)[27]), \
          "=r"((r)[28]), "=r"((r)[29]), "=r"((r)[30]), "=r"((r)[31]) \
        : "r"(addr))
#endif  // TC_OK

// ---------------------------------------------------------------------------
__global__ void reset_flags() { g_flagcnt = 0; }

// prep_x: relu(+/-x) -> 2 bf16 splits, written in tiled/swizzled layout.
__global__ __launch_bounds__(256) void prep_x(const float* __restrict__ x) {
    const int i = blockIdx.x * 256 + threadIdx.x;    // float4 index
    const int row = (i * 4) >> 11;
    const int col = (i * 4) & 2047;
    float4 v = ((const float4*)x)[i];
    float p[4] = {fmaxf(v.x, 0.f), fmaxf(v.y, 0.f), fmaxf(v.z, 0.f), fmaxf(v.w, 0.f)};
    float n[4] = {fmaxf(-v.x, 0.f), fmaxf(-v.y, 0.f), fmaxf(-v.z, 0.f), fmaxf(-v.w, 0.f)};
    union U { __nv_bfloat16 h[4]; uint2 u; };
    U sp[2], sn[2];
#pragma unroll
    for (int e = 0; e < 4; ++e) {
        split2(p[e], sp[0].h[e], sp[1].h[e]);
        split2(n[e], sn[0].h[e], sn[1].h[e]);
    }
    const size_t off = tiled_off(row, col);   // col%4==0 -> uint2 stays contiguous
#pragma unroll
    for (int s = 0; s < 2; ++s) {
        *(uint2*)((char*)g_as[0][s] + off) = sp[s].u;
        *(uint2*)((char*)g_as[1][s] + off) = sn[s].u;
    }
}

// prep_w: transpose + 2-split into tiled/swizzled planes; fp32 wT for repair.
__global__ __launch_bounds__(256) void prep_w(const float* __restrict__ wq,
                                              const float* __restrict__ wk,
                                              const float* __restrict__ wv,
                                              const float* __restrict__ wo) {
    const int z = blockIdx.z;
    const float* w = (z == 0) ? wq : (z == 1) ? wk : (z == 2) ? wv : wo;
    __shared__ float tile[32][33];
    const int tx = threadIdx.x, ty = threadIdx.y;
    const int nBase = blockIdx.x * 32, kBase = blockIdx.y * 32;
#pragma unroll
    for (int i = 0; i < 4; ++i)
        tile[ty + i * 8][tx] = w[(size_t)(kBase + ty + i * 8) * CDIM + nBase + tx];
    __syncthreads();
#pragma unroll
    for (int i = 0; i < 4; ++i) {
        float v = tile[tx][ty + i * 8];
        __nv_bfloat16 h0, h1;
        split2(v, h0, h1);
        const int nn = nBase + ty + i * 8;
        const int kk = kBase + tx;
        const size_t off = tiled_off(nn, kk);
        *(__nv_bfloat16*)((char*)g_ws[z][0] + off) = h0;
        *(__nv_bfloat16*)((char*)g_ws[z][1] + off) = h1;
        if (z < 3) g_wt[z][(size_t)nn * CDIM + kk] = v;
    }
}

// ---------------------------------------------------------------------------
// tcgen05 bf16x3 emulated GEMM, 3-stage pipeline fed by 1D bulk copies of
// pre-swizzled contiguous 16KB tiles; single driver thread.
// ---------------------------------------------------------------------------
template <bool SPIKE>
__global__ __launch_bounds__(256, 1) void gemm_tc(float* __restrict__ out) {
    extern __shared__ __align__(1024) char smem[];
    const int tid = threadIdx.x;
    const int bm = blockIdx.y, bn = blockIdx.x;

    int br = 0, wsel = 0;
    if (SPIKE) { br = blockIdx.z / 3; wsel = blockIdx.z % 3; }

#if TC_OK
    const uint32_t sbase = smem_u32(smem);
    const int wid = tid >> 5, lid = tid & 31;

    if (wid == 0) {
        asm volatile("tcgen05.alloc.cta_group::1.sync.aligned.shared::cta.b32 [%0], %1;"
                     :: "r"(sbase), "r"(128u) : "memory");
        asm volatile("tcgen05.relinquish_alloc_permit.cta_group::1.sync.aligned;");
    }
    if (tid == 0) {
#pragma unroll
        for (int s = 0; s < NSTAGE; ++s) {
            asm volatile("mbarrier.init.shared.b64 [%0], 1;"
                         :: "r"(sbase + 16 + s * 8) : "memory");   // full[s]
            asm volatile("mbarrier.init.shared.b64 [%0], 1;"
                         :: "r"(sbase + 40 + s * 8) : "memory");   // empty[s]
        }
    }
    __syncthreads();
    uint32_t tmem;
    asm volatile("ld.shared.b32 %0, [%1];" : "=r"(tmem) : "r"(sbase));

    if (tid == 0) {
        // contiguous tile streams for this CTA's row/col block
        const char* srcs[4];
        srcs[0] = (const char*)(SPIKE ? g_as[br][0] : g_xms[0]) + (size_t)bm * 32 * TILEB;
        srcs[1] = (const char*)(SPIKE ? g_as[br][1] : g_xms[1]) + (size_t)bm * 32 * TILEB;
        srcs[2] = (const char*)g_ws[SPIKE ? wsel : 3][0] + (size_t)bn * 32 * TILEB;
        srcs[3] = (const char*)g_ws[SPIKE ? wsel : 3][1] + (size_t)bn * 32 * TILEB;

        // Prologue: chunks 0..2 into stages 0..2.
#pragma unroll
        for (int s = 0; s < NSTAGE; ++s) {
            const uint32_t fb = sbase + 16 + s * 8;
            asm volatile("mbarrier.arrive.expect_tx.shared.b64 _, [%0], %1;"
                         :: "r"(fb), "r"((unsigned)STAGEB) : "memory");
#pragma unroll
            for (int ti = 0; ti < 4; ++ti)
                bulkcp(sbase + CTRLB + s * STAGEB + ti * TILEB,
                       srcs[ti] + (size_t)s * TILEB, fb);
        }

        int phF[NSTAGE] = {0, 0, 0}, phE[NSTAGE] = {0, 0, 0};
        const int PA[3] = {0, 0, 1};
        const int PB[3] = {0, 1, 0};

#pragma unroll 1
        for (int c = 0; c < NCHUNK; ++c) {
            const int s = c % NSTAGE;
            mbwait(sbase + 16 + s * 8, phF[s]);
            phF[s] ^= 1;

            const uint32_t ab = sbase + CTRLB + (uint32_t)s * STAGEB;
#pragma unroll
            for (int p = 0; p < 3; ++p) {
                const uint64_t ad = mkdesc(ab + PA[p] * TILEB);
                const uint64_t bd = mkdesc(ab + (2 + PB[p]) * TILEB);
#pragma unroll
                for (int nh = 0; nh < 2; ++nh) {
#pragma unroll
                    for (int ks = 0; ks < 4; ++ks) {
                        const uint32_t en = (c == 0 && p == 0 && ks == 0) ? 0u : 1u;
                        mma_ss(tmem + nh * 64, ad + ks * 2,
                               bd + nh * 512 + ks * 2, en);
                    }
                }
            }
            asm volatile(
                "tcgen05.commit.cta_group::1.mbarrier::arrive::one.shared::cluster.b64 [%0];"
                :: "r"(sbase + 40 + s * 8) : "memory");

            // After chunk c-1's MMAs complete, refill its stage with chunk c+2.
            if (c >= 1) {
                const int cp = c - 1;
                if (cp + NSTAGE < NCHUNK) {
                    const int sp = cp % NSTAGE;
                    mbwait(sbase + 40 + sp * 8, phE[sp]);
                    phE[sp] ^= 1;
                    const uint32_t fb = sbase + 16 + sp * 8;
                    asm volatile("mbarrier.arrive.expect_tx.shared.b64 _, [%0], %1;"
                                 :: "r"(fb), "r"((unsigned)STAGEB) : "memory");
                    const size_t q = (size_t)(cp + NSTAGE) * TILEB;
#pragma unroll
                    for (int ti = 0; ti < 4; ++ti)
                        bulkcp(sbase + CTRLB + sp * STAGEB + ti * TILEB,
                               srcs[ti] + q, fb);
                }
            }
        }
        mbwait(sbase + 40 + ((NCHUNK - 1) % NSTAGE) * 8,
               phE[(NCHUNK - 1) % NSTAGE]);
    }
    __syncthreads();
    asm volatile("tcgen05.fence::after_thread_sync;" ::: "memory");

    if (wid < 4) {
        const int row = bm * 128 + wid * 32 + lid;
#pragma unroll
        for (int cb = 0; cb < 128; cb += 32) {
            uint32_t rg[32];
            LDTM32(rg, tmem + cb);
            asm volatile("tcgen05.wait::ld.sync.aligned;" ::: "memory");
            if (SPIKE) {
                uint32_t pk[16];
#pragma unroll
                for (int jj = 0; jj < 16; ++jj) {
                    const int col0 = bn * 128 + cb + jj * 2;
                    const unsigned e0 =
                        ((unsigned)blockIdx.z << 22) | ((unsigned)row << 11) | (unsigned)col0;
                    const unsigned m0 = mask_or_flag(__uint_as_float(rg[jj * 2 + 0]), e0);
                    const unsigned m1 = mask_or_flag(__uint_as_float(rg[jj * 2 + 1]), e0 + 1);
                    pk[jj] = m0 | (m1 << 16);
                }
                uint4* dst = (uint4*)&g_masks[blockIdx.z][(size_t)row * CDIM + bn * 128 + cb];
#pragma unroll
                for (int q = 0; q < 4; ++q)
                    dst[q] = make_uint4(pk[q * 4], pk[q * 4 + 1], pk[q * 4 + 2], pk[q * 4 + 3]);
            } else {
                float4* dst = (float4*)&out[(size_t)row * CDIM + bn * 128 + cb];
#pragma unroll
                for (int q = 0; q < 8; ++q)
                    dst[q] = make_float4(__uint_as_float(rg[q * 4]),
                                         __uint_as_float(rg[q * 4 + 1]),
                                         __uint_as_float(rg[q * 4 + 2]),
                                         __uint_as_float(rg[q * 4 + 3]));
            }
        }
    }
    __syncthreads();
    if (tid == 0) {
#pragma unroll
        for (int s = 0; s < NSTAGE; ++s) {
            asm volatile("mbarrier.inval.shared.b64 [%0];" :: "r"(sbase + 16 + s * 8) : "memory");
            asm volatile("mbarrier.inval.shared.b64 [%0];" :: "r"(sbase + 40 + s * 8) : "memory");
        }
    }
    __syncthreads();
    if (wid == 0)
        asm volatile("tcgen05.dealloc.cta_group::1.sync.aligned.b32 %0, %1;"
                     :: "r"(tmem), "r"(128u));
#else
    // FFMA fallback (plain sm_103 pass): reads tiled/swizzled planes.
    const __nv_bfloat16* pa[2] = {SPIKE ? g_as[br][0] : g_xms[0],
                                  SPIKE ? g_as[br][1] : g_xms[1]};
    const __nv_bfloat16* pb[2] = {g_ws[SPIKE ? wsel : 3][0], g_ws[SPIKE ? wsel : 3][1]};

    float (*As)[128] = (float (*)[128])smem;
    float (*Bs)[128] = (float (*)[128])(smem + 16 * 128 * 4);

    float acc[8][8];
#pragma unroll
    for (int i = 0; i < 8; ++i)
#pragma unroll
        for (int j = 0; j < 8; ++j) acc[i][j] = 0.f;

    const int ty = tid >> 4, tx = tid & 15;
    const int aRow = tid >> 3, aCol = (tid & 7) * 2;   // 128x16 per pass
    const int bN = tid & 127, bKh = (tid >> 7) * 8;

    for (int kt = 0; kt < CDIM; kt += 16) {
        {
            float av[2] = {0.f, 0.f};
#pragma unroll
            for (int s = 0; s < 2; ++s)
#pragma unroll
                for (int e = 0; e < 2; ++e)
                    av[e] += __bfloat162float(*(const __nv_bfloat16*)(
                        (const char*)pa[s] + tiled_off(bm * 128 + aRow, kt + aCol + e)));
#pragma unroll
            for (int e = 0; e < 2; ++e) As[aCol + e][aRow] = av[e];
        }
        {
#pragma unroll
            for (int e = 0; e < 8; ++e) {
                float bv = 0.f;
#pragma unroll
                for (int s = 0; s < 2; ++s)
                    bv += __bfloat162float(*(const __nv_bfloat16*)(
                        (const char*)pb[s] + tiled_off(bn * 128 + bN, kt + bKh + e)));
                Bs[bKh + e][bN] = bv;
            }
        }
        __syncthreads();

#pragma unroll
        for (int k = 0; k < 16; ++k) {
            float ra[8], rb[8];
#pragma unroll
            for (int i = 0; i < 8; ++i) ra[i] = As[k][ty * 8 + i];
#pragma unroll
            for (int j = 0; j < 8; ++j) rb[j] = Bs[k][tx * 8 + j];
#pragma unroll
            for (int i = 0; i < 8; ++i)
#pragma unroll
                for (int j = 0; j < 8; ++j)
                    acc[i][j] = fmaf(ra[i], rb[j], acc[i][j]);
        }
        __syncthreads();
    }

    if (SPIKE) {
        unsigned short* Mo = g_masks[blockIdx.z];
#pragma unroll
        for (int i = 0; i < 8; ++i) {
            const int row = bm * 128 + ty * 8 + i;
#pragma unroll
            for (int j = 0; j < 8; ++j) {
                const int col = bn * 128 + tx * 8 + j;
                const unsigned enc =
                    ((unsigned)blockIdx.z << 22) | ((unsigned)row << 11) | (unsigned)col;
                Mo[(size_t)row * CDIM + col] =
                    (unsigned short)mask_or_flag(acc[i][j], enc);
            }
        }
    } else {
#pragma unroll
        for (int i = 0; i < 8; ++i) {
            const int row = bm * 128 + ty * 8 + i;
#pragma unroll
            for (int j = 0; j < 8; ++j)
                out[(size_t)row * CDIM + bn * 128 + tx * 8 + j] = acc[i][j];
        }
    }
#endif
}

// ---------------------------------------------------------------------------
// Repair: one thread per flagged element, strictly-sequential ascending-k
// fp32 fmaf chain (reference-exact summation order).
// ---------------------------------------------------------------------------
__global__ __launch_bounds__(256) void repair(const float* __restrict__ x) {
    const unsigned total = min(g_flagcnt, FLAG_CAP);
    for (unsigned e = blockIdx.x * 256 + threadIdx.x; e < total;
         e += gridDim.x * 256) {
        const unsigned enc = g_flags[e];
        const int z = enc >> 22;
        const int row = (enc >> 11) & 2047;
        const int col = enc & 2047;
        const int br = z / 3, ws = z % 3;
        const float4* xr = (const float4*)(x + (size_t)row * CDIM);
        const float4* wr = (const float4*)(g_wt[ws] + (size_t)col * CDIM);
        float acc = 0.f;
#pragma unroll 4
        for (int k4 = 0; k4 < CDIM / 4; ++k4) {
            const float4 a = xr[k4];
            const float4 b = wr[k4];
            float a0, a1, a2, a3;
            if (br) {
                a0 = fmaxf(-a.x, 0.f); a1 = fmaxf(-a.y, 0.f);
                a2 = fmaxf(-a.z, 0.f); a3 = fmaxf(-a.w, 0.f);
            } else {
                a0 = fmaxf(a.x, 0.f); a1 = fmaxf(a.y, 0.f);
                a2 = fmaxf(a.z, 0.f); a3 = fmaxf(a.w, 0.f);
            }
            acc = fmaf(a0, b.x, acc);
            acc = fmaf(a1, b.y, acc);
            acc = fmaf(a2, b.z, acc);
            acc = fmaf(a3, b.w, acc);
        }
        g_masks[z][(size_t)row * CDIM + col] = (unsigned short)if_scan_mask(acc);
    }
}

// ---------------------------------------------------------------------------
// Per-token spiking attention; writes Xm bf16 2-splits in tiled layout.
// ---------------------------------------------------------------------------
__global__ __launch_bounds__(256) void attn_k() {
    const int n = blockIdx.x;
    const int tid = threadIdx.x;

    __shared__ unsigned short Mp[3][CDIM];
    __shared__ unsigned short Mn[3][CDIM];
    __shared__ __align__(16) int8_t Qt[CDIM];
    __shared__ __align__(16) int8_t Kt[CDIM];
    __shared__ __align__(16) int8_t Vt[CDIM];
    __shared__ int attn_s[HEADS * HEADS];

    const size_t base = (size_t)n * CDIM;
    for (int c = tid; c < CDIM; c += 256) {
        Mp[0][c] = g_masks[0][base + c];
        Mp[1][c] = g_masks[1][base + c];
        Mp[2][c] = g_masks[2][base + c];
        Mn[0][c] = g_masks[3][base + c];
        Mn[1][c] = g_masks[4][base + c];
        Mn[2][c] = g_masks[5][base + c];
    }
    __syncthreads();

    int acc[8];
#pragma unroll
    for (int j = 0; j < 8; ++j) acc[j] = 0;

    const int h = tid >> 4;
    const int dbase = (tid & 15) * 8;

    for (int t = 0; t < TSTEPS; ++t) {
        for (int c = tid; c < CDIM; c += 256) {
            Qt[c] = (int8_t)(((Mp[0][c] >> t) & 1) - ((Mn[0][c] >> t) & 1));
            Kt[c] = (int8_t)(((Mp[1][c] >> t) & 1) - ((Mn[1][c] >> t) & 1));
            Vt[c] = (int8_t)(((Mp[2][c] >> t) & 1) - ((Mn[2][c] >> t) & 1));
        }
        __syncthreads();

        {
            const int hh = tid >> 4;
            const int mm = tid & 15;
            const int* qr = (const int*)(Qt + hh * 128);
            const int* kr = (const int*)(Kt + mm * 128);
            const int rot = (mm * 2) & 31;
            int s = 0;
#pragma unroll
            for (int w = 0; w < 32; ++w) {
                const int wi = (w + rot) & 31;
                s = __dp4a(qr[wi], kr[wi], s);
            }
            attn_s[hh * 16 + mm] = s;
        }
        __syncthreads();

#pragma unroll
        for (int m = 0; m < HEADS; ++m) {
            const int a = attn_s[h * 16 + m];
            const int8_t* vp = Vt + m * 128 + dbase;
#pragma unroll
            for (int j = 0; j < 8; ++j) acc[j] += a * (int)vp[j];
        }
        __syncthreads();
    }

#pragma unroll
    for (int j = 0; j < 8; ++j) {
        const float val = (float)acc[j] * 0.0125f;
        __nv_bfloat16 h0, h1;
        split2(val, h0, h1);
        const int c = (dbase + j) * HEADS + h;
        const size_t off = tiled_off(n, c);
        *(__nv_bfloat16*)((char*)g_xms[0] + off) = h0;
        *(__nv_bfloat16*)((char*)g_xms[1] + off) = h1;
    }
}

// ---------------------------------------------------------------------------
extern "C" void kernel_launch(void* const* d_in, const int* in_sizes, int n_in,
                              void* d_out, int out_size) {
    const float* x  = (const float*)d_in[0];
    const float* wq = (const float*)d_in[2];
    const float* wk = (const float*)d_in[3];
    const float* wv = (const float*)d_in[4];
    const float* wo = (const float*)d_in[5];
    float* out = (float*)d_out;

    cudaFuncSetAttribute(gemm_tc<true>, cudaFuncAttributeMaxDynamicSharedMemorySize,
                         SMEM_TOTAL);
    cudaFuncSetAttribute(gemm_tc<false>, cudaFuncAttributeMaxDynamicSharedMemorySize,
                         SMEM_TOTAL);

    reset_flags<<<1, 1>>>();
    prep_x<<<(NDIM * CDIM) / (256 * 4), 256>>>(x);
    prep_w<<<dim3(64, 64, 4), dim3(32, 8)>>>(wq, wk, wv, wo);
    gemm_tc<true><<<dim3(16, 16, 6), 256, SMEM_TOTAL>>>(nullptr);
    repair<<<1184, 256>>>(x);
    attn_k<<<NDIM, 256>>>();
    gemm_tc<false><<<dim3(16, 16, 1), 256, SMEM_TOTAL>>>(out);
}

// round 16
// speedup vs baseline: 1.1011x; 1.1011x over previous
#include <cuda_runtime.h>
#include <cuda_bf16.h>
#include <stdint.h>

#define NDIM 2048
#define CDIM 2048
#define HEADS 16
#define TSTEPS 10

#define NCHUNK 32
#define BKC    64
#define TILEB  16384             // one tile: 128 rows x 128 bytes (SW128, contiguous)
#define STAGEB (6 * TILEB)       // 2 A-splits + 4 B-tiles (2 splits x 2 rowblks) = 96KB
#define NSTAGE 2
#define CTRLB  1024
#define SMEM_TOTAL (CTRLB + NSTAGE * STAGEB)   // 197632

// idesc kind::f16, bf16 x bf16 -> f32, M=128, N=64
#define IDESC 0x8100490u

// Flag window: any |y_err| < DELTA is either provably maskless or repaired
// exactly (sequential-order fp32). IF boundaries y=1/m are >= 1/90 apart.
#define DELTA 5e-4f
#define FLAG_CAP (1u << 22)

#if defined(__CUDA_ARCH__) && \
    (defined(__CUDA_ARCH_FEAT_SM103_ALL) || defined(__CUDA_ARCH_FEAT_SM100_ALL) || \
     defined(__CUDA_ARCH_SPECIFIC__))
#define TC_OK 1
#else
#define TC_OK 0
#endif

// ---------------------------------------------------------------------------
// Global scratch. Operand planes stored TILED: plane = [rowblk 16][kchunk 32]
// of 16KB tiles, each tile SW128-swizzled exactly as the MMA smem layout.
// ---------------------------------------------------------------------------
__device__ __align__(256) unsigned short g_masks[6][NDIM * CDIM];      // 48 MB
__device__ __align__(256) __nv_bfloat16 g_as[2][2][NDIM * CDIM];       // 32 MB
__device__ __align__(256) __nv_bfloat16 g_ws[4][2][CDIM * CDIM];       // 64 MB
__device__ __align__(256) float g_wt[3][CDIM * CDIM];                  // 48 MB (repair)
__device__ __align__(256) __nv_bfloat16 g_xms[2][NDIM * CDIM];         // 16 MB
__device__ unsigned g_flagcnt;
__device__ unsigned g_flags[FLAG_CAP];                                 // 16 MB

// tiled element address (byte offset within a plane)
__device__ __forceinline__ size_t tiled_off(int row, int col) {
    const size_t tile = (size_t)(row >> 7) * 32 + (col >> 6);
    uint32_t inner = (uint32_t)(row & 127) * 128 + (col & 63) * 2;
    inner ^= (inner >> 3) & 0x70;            // SW128
    return tile * TILEB + inner;
}

// ---------------------------------------------------------------------------
__device__ __forceinline__ void split2(float a, __nv_bfloat16& h0, __nv_bfloat16& h1) {
    h0 = __float2bfloat16_rn(a);
    h1 = __float2bfloat16_rn(a - __bfloat162float(h0));
}

__device__ __forceinline__ unsigned if_scan_mask(float y) {
    float v = 0.f;
    unsigned m = 0;
#pragma unroll
    for (int t = 0; t < TSTEPS; ++t) {
        v += y;
        if (v >= 1.0f) { m |= (1u << t); v = 0.f; }
    }
    return m;
}

__device__ __forceinline__ unsigned mask_or_flag(float y, unsigned enc) {
    const unsigned mlo = if_scan_mask(y - DELTA);
    const unsigned mhi = if_scan_mask(y + DELTA);
    const bool flag = (mlo != mhi);
    const unsigned bal = __ballot_sync(0xFFFFFFFFu, flag);
    if (bal) {
        const int lane = threadIdx.x & 31;
        const int leader = __ffs(bal) - 1;
        unsigned base = 0;
        if (lane == leader) base = atomicAdd(&g_flagcnt, (unsigned)__popc(bal));
        base = __shfl_sync(0xFFFFFFFFu, base, leader);
        if (flag) {
            const unsigned off = (unsigned)__popc(bal & ((1u << lane) - 1u));
            if (base + off < FLAG_CAP) g_flags[base + off] = enc;
        }
    }
    return mlo;
}

#if TC_OK
// ---------------------------------------------------------------------------
// tcgen05 / bulk-copy PTX helpers (arch-specific pass only)
// ---------------------------------------------------------------------------
__device__ __forceinline__ uint32_t smem_u32(const void* p) {
    return (uint32_t)__cvta_generic_to_shared(p);
}
__device__ __forceinline__ uint64_t mkdesc(uint32_t addr) {
    return 0x4000404000010000ULL | (uint64_t)((addr >> 4) & 0x3FFF);
}
__device__ __forceinline__ void mma_ss(uint32_t d, uint64_t ad, uint64_t bd, uint32_t en) {
    asm volatile(
        "{\n\t.reg .pred p;\n\tsetp.ne.u32 p, %5, 0;\n\t"
        "tcgen05.mma.cta_group::1.kind::f16 [%0], %1, %2, %3, {%4, %4, %4, %4}, p;\n\t}"
        :: "r"(d), "l"(ad), "l"(bd), "r"(IDESC), "r"(0u), "r"(en) : "memory");
}
// Non-sleeping poll wait (test_wait, 149cy/poll) — avoids HW-sleep wake latency.
__device__ __forceinline__ void mbpoll(uint32_t mb, int phase) {
    asm volatile(
        "{\n\t.reg .pred P;\n\tPL%=:\n\t"
        "mbarrier.test_wait.parity.acquire.cta.shared::cta.b64 P, [%0], %1;\n\t"
        "@!P bra PL%=;\n\t}"
        :: "r"(mb), "r"(phase) : "memory");
}
// 1D bulk copy: 16KB contiguous GMEM -> SMEM, mbarrier complete_tx.
__device__ __forceinline__ void bulkcp(uint32_t dst, const void* src, uint32_t mbar) {
    asm volatile(
        "cp.async.bulk.shared::cluster.global.mbarrier::complete_tx::bytes "
        "[%0], [%1], %2, [%3];"
        :: "r"(dst), "l"(src), "r"((unsigned)TILEB), "r"(mbar) : "memory");
}
#define LDTM32(r, addr) \
    asm volatile( \
        "tcgen05.ld.sync.aligned.32x32b.x32.b32 " \
        "{%0, %1, %2, %3, %4, %5, %6, %7, " \
        " %8, %9, %10, %11, %12, %13, %14, %15, " \
        " %16, %17, %18, %19, %20, %21, %22, %23, " \
        " %24, %25, %26, %27, %28, %29, %30, %31}, [%32];" \
        : "=r"((r)[0]),  "=r"((r)[1]),  "=r"((r)[2]),  "=r"((r)[3]), \
          "=r"((r)[4]),  "=r"((r)[5]),  "=r"((r)[6]),  "=r"((r)[7]), \
          "=r"((r)[8]),  "=r"((r)[9]),  "=r"((r)[10]), "=r"((r)[11]), \
          "=r"((r)[12]), "=r"((r)[13]), "=r"((r)[14]), "=r"((r)[15]), \
          "=r"((r)[16]), "=r"((r)[17]), "=r"((r)[18]), "=r"((r)[19]), \
          "=r"((r)[20]), "=r"((r)[21]), "=r"((r)[22]), "=r"((r)[23]), \
          "=r"((r)[24]), "=r"((r)[25]), "=r"((r)[26]), "=r"((r)[27]), \
          "=r"((r)[28]), "=r"((r)[29]), "=r"((r)[30]), "=r"((r)[31]) \
        : "r"(addr))
#endif  // TC_OK

// ---------------------------------------------------------------------------
__global__ void reset_flags() { g_flagcnt = 0; }

// prep_x: relu(+/-x) -> 2 bf16 splits, written in tiled/swizzled layout.
__global__ __launch_bounds__(256) void prep_x(const float* __restrict__ x) {
    const int i = blockIdx.x * 256 + threadIdx.x;    // float4 index
    const int row = (i * 4) >> 11;
    const int col = (i * 4) & 2047;
    float4 v = ((const float4*)x)[i];
    float p[4] = {fmaxf(v.x, 0.f), fmaxf(v.y, 0.f), fmaxf(v.z, 0.f), fmaxf(v.w, 0.f)};
    float n[4] = {fmaxf(-v.x, 0.f), fmaxf(-v.y, 0.f), fmaxf(-v.z, 0.f), fmaxf(-v.w, 0.f)};
    union U { __nv_bfloat16 h[4]; uint2 u; };
    U sp[2], sn[2];
#pragma unroll
    for (int e = 0; e < 4; ++e) {
        split2(p[e], sp[0].h[e], sp[1].h[e]);
        split2(n[e], sn[0].h[e], sn[1].h[e]);
    }
    const size_t off = tiled_off(row, col);
#pragma unroll
    for (int s = 0; s < 2; ++s) {
        *(uint2*)((char*)g_as[0][s] + off) = sp[s].u;
        *(uint2*)((char*)g_as[1][s] + off) = sn[s].u;
    }
}

// prep_w: transpose + 2-split into tiled/swizzled planes; fp32 wT for repair.
__global__ __launch_bounds__(256) void prep_w(const float* __restrict__ wq,
                                              const float* __restrict__ wk,
                                              const float* __restrict__ wv,
                                              const float* __restrict__ wo) {
    const int z = blockIdx.z;
    const float* w = (z == 0) ? wq : (z == 1) ? wk : (z == 2) ? wv : wo;
    __shared__ float tile[32][33];
    const int tx = threadIdx.x, ty = threadIdx.y;
    const int nBase = blockIdx.x * 32, kBase = blockIdx.y * 32;
#pragma unroll
    for (int i = 0; i < 4; ++i)
        tile[ty + i * 8][tx] = w[(size_t)(kBase + ty + i * 8) * CDIM + nBase + tx];
    __syncthreads();
#pragma unroll
    for (int i = 0; i < 4; ++i) {
        float v = tile[tx][ty + i * 8];
        __nv_bfloat16 h0, h1;
        split2(v, h0, h1);
        const int nn = nBase + ty + i * 8;
        const int kk = kBase + tx;
        const size_t off = tiled_off(nn, kk);
        *(__nv_bfloat16*)((char*)g_ws[z][0] + off) = h0;
        *(__nv_bfloat16*)((char*)g_ws[z][1] + off) = h1;
        if (z < 3) g_wt[z][(size_t)nn * CDIM + kk] = v;
    }
}

// ---------------------------------------------------------------------------
// tcgen05 bf16x3 emulated GEMM, 128x256 CTA tile, 2-stage bulk-copy pipeline,
// polling waits, single driver thread.
// ---------------------------------------------------------------------------
template <bool SPIKE>
__global__ __launch_bounds__(256, 1) void gemm_tc(float* __restrict__ out) {
    extern __shared__ __align__(1024) char smem[];
    const int tid = threadIdx.x;
    const int bm = blockIdx.y, bn = blockIdx.x;   // bn covers 256 cols

    int br = 0, wsel = 0;
    if (SPIKE) { br = blockIdx.z / 3; wsel = blockIdx.z % 3; }

#if TC_OK
    const uint32_t sbase = smem_u32(smem);
    const int wid = tid >> 5, lid = tid & 31;

    if (wid == 0) {
        asm volatile("tcgen05.alloc.cta_group::1.sync.aligned.shared::cta.b32 [%0], %1;"
                     :: "r"(sbase), "r"(256u) : "memory");
        asm volatile("tcgen05.relinquish_alloc_permit.cta_group::1.sync.aligned;");
    }
    if (tid == 0) {
#pragma unroll
        for (int s = 0; s < NSTAGE; ++s) {
            asm volatile("mbarrier.init.shared.b64 [%0], 1;"
                         :: "r"(sbase + 16 + s * 8) : "memory");   // full[s]
            asm volatile("mbarrier.init.shared.b64 [%0], 1;"
                         :: "r"(sbase + 40 + s * 8) : "memory");   // empty[s]
        }
    }
    __syncthreads();
    uint32_t tmem;
    asm volatile("ld.shared.b32 %0, [%1];" : "=r"(tmem) : "r"(sbase));

    if (tid == 0) {
        // 6 contiguous tile streams: A split0/1 (rowblk bm), B split0/1 x rowblk 2bn,2bn+1
        const char* srcs[6];
        srcs[0] = (const char*)(SPIKE ? g_as[br][0] : g_xms[0]) + (size_t)bm * 32 * TILEB;
        srcs[1] = (const char*)(SPIKE ? g_as[br][1] : g_xms[1]) + (size_t)bm * 32 * TILEB;
        const char* bw0 = (const char*)g_ws[SPIKE ? wsel : 3][0];
        const char* bw1 = (const char*)g_ws[SPIKE ? wsel : 3][1];
        srcs[2] = bw0 + (size_t)(bn * 2 + 0) * 32 * TILEB;
        srcs[3] = bw0 + (size_t)(bn * 2 + 1) * 32 * TILEB;
        srcs[4] = bw1 + (size_t)(bn * 2 + 0) * 32 * TILEB;
        srcs[5] = bw1 + (size_t)(bn * 2 + 1) * 32 * TILEB;

        // Prologue: chunks 0,1 -> stages 0,1.
#pragma unroll
        for (int s = 0; s < NSTAGE; ++s) {
            const uint32_t fb = sbase + 16 + s * 8;
            asm volatile("mbarrier.arrive.expect_tx.shared.b64 _, [%0], %1;"
                         :: "r"(fb), "r"((unsigned)STAGEB) : "memory");
#pragma unroll
            for (int ti = 0; ti < 6; ++ti)
                bulkcp(sbase + CTRLB + s * STAGEB + ti * TILEB,
                       srcs[ti] + (size_t)s * TILEB, fb);
        }

        int phF[NSTAGE] = {0, 0}, phE[NSTAGE] = {0, 0};
        const int PA[3] = {0, 0, 1};
        const int PB[3] = {0, 1, 0};

#pragma unroll 1
        for (int c = 0; c < NCHUNK; ++c) {
            const int s = c & 1;
            mbpoll(sbase + 16 + s * 8, phF[s]);
            phF[s] ^= 1;

            const uint32_t ab = sbase + CTRLB + (uint32_t)s * STAGEB;
#pragma unroll
            for (int p = 0; p < 3; ++p) {
                const uint64_t ad = mkdesc(ab + PA[p] * TILEB);
#pragma unroll
                for (int nb = 0; nb < 4; ++nb) {
                    const uint64_t bd =
                        mkdesc(ab + (2 + PB[p] * 2 + (nb >> 1)) * TILEB) + (nb & 1) * 512;
#pragma unroll
                    for (int ks = 0; ks < 4; ++ks) {
                        const uint32_t en = (c == 0 && p == 0 && ks == 0) ? 0u : 1u;
                        mma_ss(tmem + nb * 64, ad + ks * 2, bd + ks * 2, en);
                    }
                }
            }
            asm volatile(
                "tcgen05.commit.cta_group::1.mbarrier::arrive::one.shared::cluster.b64 [%0];"
                :: "r"(sbase + 40 + s * 8) : "memory");

            // After chunk c-1's MMAs complete, refill its stage with chunk c+1.
            if (c >= 1) {
                const int sp = (c - 1) & 1;
                mbpoll(sbase + 40 + sp * 8, phE[sp]);
                phE[sp] ^= 1;
                if (c + 1 < NCHUNK) {
                    const uint32_t fb = sbase + 16 + sp * 8;
                    asm volatile("mbarrier.arrive.expect_tx.shared.b64 _, [%0], %1;"
                                 :: "r"(fb), "r"((unsigned)STAGEB) : "memory");
                    const size_t q = (size_t)(c + 1) * TILEB;
#pragma unroll
                    for (int ti = 0; ti < 6; ++ti)
                        bulkcp(sbase + CTRLB + sp * STAGEB + ti * TILEB,
                               srcs[ti] + q, fb);
                }
            }
        }
        mbpoll(sbase + 40 + ((NCHUNK - 1) & 1) * 8, phE[(NCHUNK - 1) & 1]);
    }
    __syncthreads();
    asm volatile("tcgen05.fence::after_thread_sync;" ::: "memory");

    if (wid < 4) {
        const int row = bm * 128 + wid * 32 + lid;
#pragma unroll 1
        for (int cb = 0; cb < 256; cb += 32) {
            uint32_t rg[32];
            LDTM32(rg, tmem + cb);
            asm volatile("tcgen05.wait::ld.sync.aligned;" ::: "memory");
            if (SPIKE) {
                uint32_t pk[16];
#pragma unroll
                for (int jj = 0; jj < 16; ++jj) {
                    const int col0 = bn * 256 + cb + jj * 2;
                    const unsigned e0 =
                        ((unsigned)blockIdx.z << 22) | ((unsigned)row << 11) | (unsigned)col0;
                    const unsigned m0 = mask_or_flag(__uint_as_float(rg[jj * 2 + 0]), e0);
                    const unsigned m1 = mask_or_flag(__uint_as_float(rg[jj * 2 + 1]), e0 + 1);
                    pk[jj] = m0 | (m1 << 16);
                }
                uint4* dst = (uint4*)&g_masks[blockIdx.z][(size_t)row * CDIM + bn * 256 + cb];
#pragma unroll
                for (int q = 0; q < 4; ++q)
                    dst[q] = make_uint4(pk[q * 4], pk[q * 4 + 1], pk[q * 4 + 2], pk[q * 4 + 3]);
            } else {
                float4* dst = (float4*)&out[(size_t)row * CDIM + bn * 256 + cb];
#pragma unroll
                for (int q = 0; q < 8; ++q)
                    dst[q] = make_float4(__uint_as_float(rg[q * 4]),
                                         __uint_as_float(rg[q * 4 + 1]),
                                         __uint_as_float(rg[q * 4 + 2]),
                                         __uint_as_float(rg[q * 4 + 3]));
            }
        }
    }
    __syncthreads();
    if (tid == 0) {
#pragma unroll
        for (int s = 0; s < NSTAGE; ++s) {
            asm volatile("mbarrier.inval.shared.b64 [%0];" :: "r"(sbase + 16 + s * 8) : "memory");
            asm volatile("mbarrier.inval.shared.b64 [%0];" :: "r"(sbase + 40 + s * 8) : "memory");
        }
    }
    __syncthreads();
    if (wid == 0)
        asm volatile("tcgen05.dealloc.cta_group::1.sync.aligned.b32 %0, %1;"
                     :: "r"(tmem), "r"(256u));
#else
    // FFMA fallback (plain sm_103 pass): two 128-col halves sequentially.
    const __nv_bfloat16* pa[2] = {SPIKE ? g_as[br][0] : g_xms[0],
                                  SPIKE ? g_as[br][1] : g_xms[1]};
    const __nv_bfloat16* pb[2] = {g_ws[SPIKE ? wsel : 3][0], g_ws[SPIKE ? wsel : 3][1]};

    float (*As)[128] = (float (*)[128])smem;
    float (*Bs)[128] = (float (*)[128])(smem + 16 * 128 * 4);

    const int ty = tid >> 4, tx = tid & 15;
    const int aRow = tid >> 3, aCol = (tid & 7) * 2;
    const int bN = tid & 127, bKh = (tid >> 7) * 8;

    for (int nh2 = 0; nh2 < 2; ++nh2) {
        const int ncol = bn * 256 + nh2 * 128;
        float acc[8][8];
#pragma unroll
        for (int i = 0; i < 8; ++i)
#pragma unroll
            for (int j = 0; j < 8; ++j) acc[i][j] = 0.f;

        for (int kt = 0; kt < CDIM; kt += 16) {
            {
                float av[2] = {0.f, 0.f};
#pragma unroll
                for (int s = 0; s < 2; ++s)
#pragma unroll
                    for (int e = 0; e < 2; ++e)
                        av[e] += __bfloat162float(*(const __nv_bfloat16*)(
                            (const char*)pa[s] + tiled_off(bm * 128 + aRow, kt + aCol + e)));
#pragma unroll
                for (int e = 0; e < 2; ++e) As[aCol + e][aRow] = av[e];
            }
            {
#pragma unroll
                for (int e = 0; e < 8; ++e) {
                    float bv = 0.f;
#pragma unroll
                    for (int s = 0; s < 2; ++s)
                        bv += __bfloat162float(*(const __nv_bfloat16*)(
                            (const char*)pb[s] + tiled_off(ncol + bN, kt + bKh + e)));
                    Bs[bKh + e][bN] = bv;
                }
            }
            __syncthreads();

#pragma unroll
            for (int k = 0; k < 16; ++k) {
                float ra[8], rb[8];
#pragma unroll
                for (int i = 0; i < 8; ++i) ra[i] = As[k][ty * 8 + i];
#pragma unroll
                for (int j = 0; j < 8; ++j) rb[j] = Bs[k][tx * 8 + j];
#pragma unroll
                for (int i = 0; i < 8; ++i)
#pragma unroll
                    for (int j = 0; j < 8; ++j)
                        acc[i][j] = fmaf(ra[i], rb[j], acc[i][j]);
            }
            __syncthreads();
        }

        if (SPIKE) {
            unsigned short* Mo = g_masks[blockIdx.z];
#pragma unroll
            for (int i = 0; i < 8; ++i) {
                const int row = bm * 128 + ty * 8 + i;
#pragma unroll
                for (int j = 0; j < 8; ++j) {
                    const int col = ncol + tx * 8 + j;
                    const unsigned enc =
                        ((unsigned)blockIdx.z << 22) | ((unsigned)row << 11) | (unsigned)col;
                    Mo[(size_t)row * CDIM + col] =
                        (unsigned short)mask_or_flag(acc[i][j], enc);
                }
            }
        } else {
#pragma unroll
            for (int i = 0; i < 8; ++i) {
                const int row = bm * 128 + ty * 8 + i;
#pragma unroll
                for (int j = 0; j < 8; ++j)
                    out[(size_t)row * CDIM + ncol + tx * 8 + j] = acc[i][j];
            }
        }
        __syncthreads();
    }
#endif
}

// ---------------------------------------------------------------------------
// Repair: one thread per flagged element, strictly-sequential ascending-k
// fp32 fmaf chain (reference-exact summation order).
// ---------------------------------------------------------------------------
__global__ __launch_bounds__(256) void repair(const float* __restrict__ x) {
    const unsigned total = min(g_flagcnt, FLAG_CAP);
    for (unsigned e = blockIdx.x * 256 + threadIdx.x; e < total;
         e += gridDim.x * 256) {
        const unsigned enc = g_flags[e];
        const int z = enc >> 22;
        const int row = (enc >> 11) & 2047;
        const int col = enc & 2047;
        const int br = z / 3, ws = z % 3;
        const float4* xr = (const float4*)(x + (size_t)row * CDIM);
        const float4* wr = (const float4*)(g_wt[ws] + (size_t)col * CDIM);
        float acc = 0.f;
#pragma unroll 4
        for (int k4 = 0; k4 < CDIM / 4; ++k4) {
            const float4 a = xr[k4];
            const float4 b = wr[k4];
            float a0, a1, a2, a3;
            if (br) {
                a0 = fmaxf(-a.x, 0.f); a1 = fmaxf(-a.y, 0.f);
                a2 = fmaxf(-a.z, 0.f); a3 = fmaxf(-a.w, 0.f);
            } else {
                a0 = fmaxf(a.x, 0.f); a1 = fmaxf(a.y, 0.f);
                a2 = fmaxf(a.z, 0.f); a3 = fmaxf(a.w, 0.f);
            }
            acc = fmaf(a0, b.x, acc);
            acc = fmaf(a1, b.y, acc);
            acc = fmaf(a2, b.z, acc);
            acc = fmaf(a3, b.w, acc);
        }
        g_masks[z][(size_t)row * CDIM + col] = (unsigned short)if_scan_mask(acc);
    }
}

// ---------------------------------------------------------------------------
// Per-token spiking attention; writes Xm bf16 2-splits in tiled layout.
// ---------------------------------------------------------------------------
__global__ __launch_bounds__(256) void attn_k() {
    const int n = blockIdx.x;
    const int tid = threadIdx.x;

    __shared__ unsigned short Mp[3][CDIM];
    __shared__ unsigned short Mn[3][CDIM];
    __shared__ __align__(16) int8_t Qt[CDIM];
    __shared__ __align__(16) int8_t Kt[CDIM];
    __shared__ __align__(16) int8_t Vt[CDIM];
    __shared__ int attn_s[HEADS * HEADS];

    const size_t base = (size_t)n * CDIM;
    for (int c = tid; c < CDIM; c += 256) {
        Mp[0][c] = g_masks[0][base + c];
        Mp[1][c] = g_masks[1][base + c];
        Mp[2][c] = g_masks[2][base + c];
        Mn[0][c] = g_masks[3][base + c];
        Mn[1][c] = g_masks[4][base + c];
        Mn[2][c] = g_masks[5][base + c];
    }
    __syncthreads();

    int acc[8];
#pragma unroll
    for (int j = 0; j < 8; ++j) acc[j] = 0;

    const int h = tid >> 4;
    const int dbase = (tid & 15) * 8;

    for (int t = 0; t < TSTEPS; ++t) {
        for (int c = tid; c < CDIM; c += 256) {
            Qt[c] = (int8_t)(((Mp[0][c] >> t) & 1) - ((Mn[0][c] >> t) & 1));
            Kt[c] = (int8_t)(((Mp[1][c] >> t) & 1) - ((Mn[1][c] >> t) & 1));
            Vt[c] = (int8_t)(((Mp[2][c] >> t) & 1) - ((Mn[2][c] >> t) & 1));
        }
        __syncthreads();

        {
            const int hh = tid >> 4;
            const int mm = tid & 15;
            const int* qr = (const int*)(Qt + hh * 128);
            const int* kr = (const int*)(Kt + mm * 128);
            const int rot = (mm * 2) & 31;
            int s = 0;
#pragma unroll
            for (int w = 0; w < 32; ++w) {
                const int wi = (w + rot) & 31;
                s = __dp4a(qr[wi], kr[wi], s);
            }
            attn_s[hh * 16 + mm] = s;
        }
        __syncthreads();

#pragma unroll
        for (int m = 0; m < HEADS; ++m) {
            const int a = attn_s[h * 16 + m];
            const int8_t* vp = Vt + m * 128 + dbase;
#pragma unroll
            for (int j = 0; j < 8; ++j) acc[j] += a * (int)vp[j];
        }
        __syncthreads();
    }

#pragma unroll
    for (int j = 0; j < 8; ++j) {
        const float val = (float)acc[j] * 0.0125f;
        __nv_bfloat16 h0, h1;
        split2(val, h0, h1);
        const int c = (dbase + j) * HEADS + h;
        const size_t off = tiled_off(n, c);
        *(__nv_bfloat16*)((char*)g_xms[0] + off) = h0;
        *(__nv_bfloat16*)((char*)g_xms[1] + off) = h1;
    }
}

// ---------------------------------------------------------------------------
extern "C" void kernel_launch(void* const* d_in, const int* in_sizes, int n_in,
                              void* d_out, int out_size) {
    const float* x  = (const float*)d_in[0];
    const float* wq = (const float*)d_in[2];
    const float* wk = (const float*)d_in[3];
    const float* wv = (const float*)d_in[4];
    const float* wo = (const float*)d_in[5];
    float* out = (float*)d_out;

    cudaFuncSetAttribute(gemm_tc<true>, cudaFuncAttributeMaxDynamicSharedMemorySize,
                         SMEM_TOTAL);
    cudaFuncSetAttribute(gemm_tc<false>, cudaFuncAttributeMaxDynamicSharedMemorySize,
                         SMEM_TOTAL);

    reset_flags<<<1, 1>>>();
    prep_x<<<(NDIM * CDIM) / (256 * 4), 256>>>(x);
    prep_w<<<dim3(64, 64, 4), dim3(32, 8)>>>(wq, wk, wv, wo);
    gemm_tc<true><<<dim3(8, 16, 6), 256, SMEM_TOTAL>>>(nullptr);
    repair<<<1184, 256>>>(x);
    attn_k<<<NDIM, 256>>>();
    gemm_tc<false><<<dim3(8, 16, 1), 256, SMEM_TOTAL>>>(out);
}

// round 17
// speedup vs baseline: 1.2431x; 1.1289x over previous
#include <cuda_runtime.h>
#include <cuda_bf16.h>
#include <stdint.h>

#define NDIM 2048
#define CDIM 2048
#define HEADS 16
#define TSTEPS 10

#define NCHUNK 32
#define BKC    64
#define TILEB  16384             // one tile: 128 rows x 128 bytes (SW128, contiguous)
#define STAGEB (6 * TILEB)       // 2 A-splits + 4 B-tiles (2 splits x 2 rowblks) = 96KB
#define NSTAGE 2
#define CTRLB  1024
#define SMEM_TOTAL (CTRLB + NSTAGE * STAGEB)   // 197632

// idesc kind::f16, bf16 x bf16 -> f32, M=128, N=256
// (1<<4)|(1<<7)|(1<<10)|((256/8)<<17)|((128/16)<<24) = 0x8400490
#define IDESC 0x8400490u

// Flag window: any |y_err| < DELTA is either provably maskless or repaired
// exactly (sequential-order fp32). IF boundaries y=1/m are >= 1/90 apart.
#define DELTA 5e-4f
#define FLAG_CAP (1u << 22)

#if defined(__CUDA_ARCH__) && \
    (defined(__CUDA_ARCH_FEAT_SM103_ALL) || defined(__CUDA_ARCH_FEAT_SM100_ALL) || \
     defined(__CUDA_ARCH_SPECIFIC__))
#define TC_OK 1
#else
#define TC_OK 0
#endif

// ---------------------------------------------------------------------------
// Global scratch. Operand planes stored TILED: plane = [rowblk 16][kchunk 32]
// of 16KB tiles, each tile SW128-swizzled exactly as the MMA smem layout.
// ---------------------------------------------------------------------------
__device__ __align__(256) unsigned short g_masks[6][NDIM * CDIM];      // 48 MB
__device__ __align__(256) __nv_bfloat16 g_as[2][2][NDIM * CDIM];       // 32 MB
__device__ __align__(256) __nv_bfloat16 g_ws[4][2][CDIM * CDIM];       // 64 MB
__device__ __align__(256) float g_wt[3][CDIM * CDIM];                  // 48 MB (repair)
__device__ __align__(256) __nv_bfloat16 g_xms[2][NDIM * CDIM];         // 16 MB
__device__ unsigned g_flagcnt;
__device__ unsigned g_flags[FLAG_CAP];                                 // 16 MB

// tiled element address (byte offset within a plane)
__device__ __forceinline__ size_t tiled_off(int row, int col) {
    const size_t tile = (size_t)(row >> 7) * 32 + (col >> 6);
    uint32_t inner = (uint32_t)(row & 127) * 128 + (col & 63) * 2;
    inner ^= (inner >> 3) & 0x70;            // SW128
    return tile * TILEB + inner;
}

// ---------------------------------------------------------------------------
__device__ __forceinline__ void split2(float a, __nv_bfloat16& h0, __nv_bfloat16& h1) {
    h0 = __float2bfloat16_rn(a);
    h1 = __float2bfloat16_rn(a - __bfloat162float(h0));
}

__device__ __forceinline__ unsigned if_scan_mask(float y) {
    float v = 0.f;
    unsigned m = 0;
#pragma unroll
    for (int t = 0; t < TSTEPS; ++t) {
        v += y;
        if (v >= 1.0f) { m |= (1u << t); v = 0.f; }
    }
    return m;
}

__device__ __forceinline__ unsigned mask_or_flag(float y, unsigned enc) {
    const unsigned mlo = if_scan_mask(y - DELTA);
    const unsigned mhi = if_scan_mask(y + DELTA);
    const bool flag = (mlo != mhi);
    const unsigned bal = __ballot_sync(0xFFFFFFFFu, flag);
    if (bal) {
        const int lane = threadIdx.x & 31;
        const int leader = __ffs(bal) - 1;
        unsigned base = 0;
        if (lane == leader) base = atomicAdd(&g_flagcnt, (unsigned)__popc(bal));
        base = __shfl_sync(0xFFFFFFFFu, base, leader);
        if (flag) {
            const unsigned off = (unsigned)__popc(bal & ((1u << lane) - 1u));
            if (base + off < FLAG_CAP) g_flags[base + off] = enc;
        }
    }
    return mlo;
}

#if TC_OK
// ---------------------------------------------------------------------------
// tcgen05 / bulk-copy PTX helpers (arch-specific pass only)
// ---------------------------------------------------------------------------
__device__ __forceinline__ uint32_t smem_u32(const void* p) {
    return (uint32_t)__cvta_generic_to_shared(p);
}
__device__ __forceinline__ uint64_t mkdesc(uint32_t addr) {
    return 0x4000404000010000ULL | (uint64_t)((addr >> 4) & 0x3FFF);
}
__device__ __forceinline__ void mma_ss(uint32_t d, uint64_t ad, uint64_t bd, uint32_t en) {
    asm volatile(
        "{\n\t.reg .pred p;\n\tsetp.ne.u32 p, %5, 0;\n\t"
        "tcgen05.mma.cta_group::1.kind::f16 [%0], %1, %2, %3, {%4, %4, %4, %4}, p;\n\t}"
        :: "r"(d), "l"(ad), "l"(bd), "r"(IDESC), "r"(0u), "r"(en) : "memory");
}
// Non-sleeping poll wait (test_wait) — avoids HW-sleep wake latency.
__device__ __forceinline__ void mbpoll(uint32_t mb, int phase) {
    asm volatile(
        "{\n\t.reg .pred P;\n\tPL%=:\n\t"
        "mbarrier.test_wait.parity.acquire.cta.shared::cta.b64 P, [%0], %1;\n\t"
        "@!P bra PL%=;\n\t}"
        :: "r"(mb), "r"(phase) : "memory");
}
// 1D bulk copy: 16KB contiguous GMEM -> SMEM, mbarrier complete_tx.
__device__ __forceinline__ void bulkcp(uint32_t dst, const void* src, uint32_t mbar) {
    asm volatile(
        "cp.async.bulk.shared::cluster.global.mbarrier::complete_tx::bytes "
        "[%0], [%1], %2, [%3];"
        :: "r"(dst), "l"(src), "r"((unsigned)TILEB), "r"(mbar) : "memory");
}
#define LDTM32(r, addr) \
    asm volatile( \
        "tcgen05.ld.sync.aligned.32x32b.x32.b32 " \
        "{%0, %1, %2, %3, %4, %5, %6, %7, " \
        " %8, %9, %10, %11, %12, %13, %14, %15, " \
        " %16, %17, %18, %19, %20, %21, %22, %23, " \
        " %24, %25, %26, %27, %28, %29, %30, %31}, [%32];" \
        : "=r"((r)[0]),  "=r"((r)[1]),  "=r"((r)[2]),  "=r"((r)[3]), \
          "=r"((r)[4]),  "=r"((r)[5]),  "=r"((r)[6]),  "=r"((r)[7]), \
          "=r"((r)[8]),  "=r"((r)[9]),  "=r"((r)[10]), "=r"((r)[11]), \
          "=r"((r)[12]), "=r"((r)[13]), "=r"((r)[14]), "=r"((r)[15]), \
          "=r"((r)[16]), "=r"((r)[17]), "=r"((r)[18]), "=r"((r)[19]), \
          "=r"((r)[20]), "=r"((r)[21]), "=r"((r)[22]), "=r"((r)[23]), \
          "=r"((r)[24]), "=r"((r)[25]), "=r"((r)[26]), "=r"((r)[27]), \
          "=r"((r)[28]), "=r"((r)[29]), "=r"((r)[30]), "=r"((r)[31]) \
        : "r"(addr))
#endif  // TC_OK

// ---------------------------------------------------------------------------
__global__ void reset_flags() { g_flagcnt = 0; }

// prep_x: relu(+/-x) -> 2 bf16 splits, written in tiled/swizzled layout.
__global__ __launch_bounds__(256) void prep_x(const float* __restrict__ x) {
    const int i = blockIdx.x * 256 + threadIdx.x;    // float4 index
    const int row = (i * 4) >> 11;
    const int col = (i * 4) & 2047;
    float4 v = ((const float4*)x)[i];
    float p[4] = {fmaxf(v.x, 0.f), fmaxf(v.y, 0.f), fmaxf(v.z, 0.f), fmaxf(v.w, 0.f)};
    float n[4] = {fmaxf(-v.x, 0.f), fmaxf(-v.y, 0.f), fmaxf(-v.z, 0.f), fmaxf(-v.w, 0.f)};
    union U { __nv_bfloat16 h[4]; uint2 u; };
    U sp[2], sn[2];
#pragma unroll
    for (int e = 0; e < 4; ++e) {
        split2(p[e], sp[0].h[e], sp[1].h[e]);
        split2(n[e], sn[0].h[e], sn[1].h[e]);
    }
    const size_t off = tiled_off(row, col);
#pragma unroll
    for (int s = 0; s < 2; ++s) {
        *(uint2*)((char*)g_as[0][s] + off) = sp[s].u;
        *(uint2*)((char*)g_as[1][s] + off) = sn[s].u;
    }
}

// prep_w: transpose + 2-split into tiled/swizzled planes; fp32 wT for repair.
__global__ __launch_bounds__(256) void prep_w(const float* __restrict__ wq,
                                              const float* __restrict__ wk,
                                              const float* __restrict__ wv,
                                              const float* __restrict__ wo) {
    const int z = blockIdx.z;
    const float* w = (z == 0) ? wq : (z == 1) ? wk : (z == 2) ? wv : wo;
    __shared__ float tile[32][33];
    const int tx = threadIdx.x, ty = threadIdx.y;
    const int nBase = blockIdx.x * 32, kBase = blockIdx.y * 32;
#pragma unroll
    for (int i = 0; i < 4; ++i)
        tile[ty + i * 8][tx] = w[(size_t)(kBase + ty + i * 8) * CDIM + nBase + tx];
    __syncthreads();
#pragma unroll
    for (int i = 0; i < 4; ++i) {
        float v = tile[tx][ty + i * 8];
        __nv_bfloat16 h0, h1;
        split2(v, h0, h1);
        const int nn = nBase + ty + i * 8;
        const int kk = kBase + tx;
        const size_t off = tiled_off(nn, kk);
        *(__nv_bfloat16*)((char*)g_ws[z][0] + off) = h0;
        *(__nv_bfloat16*)((char*)g_ws[z][1] + off) = h1;
        if (z < 3) g_wt[z][(size_t)nn * CDIM + kk] = v;
    }
}

// ---------------------------------------------------------------------------
// tcgen05 bf16x3 emulated GEMM, 128x256 CTA tile, single N=256 MMA per
// (product, K-step): 12 MMAs/chunk, 2-stage bulk-copy pipeline, polling waits.
// ---------------------------------------------------------------------------
template <bool SPIKE>
__global__ __launch_bounds__(256, 1) void gemm_tc(float* __restrict__ out) {
    extern __shared__ __align__(1024) char smem[];
    const int tid = threadIdx.x;
    const int bm = blockIdx.y, bn = blockIdx.x;   // bn covers 256 cols

    int br = 0, wsel = 0;
    if (SPIKE) { br = blockIdx.z / 3; wsel = blockIdx.z % 3; }

#if TC_OK
    const uint32_t sbase = smem_u32(smem);
    const int wid = tid >> 5, lid = tid & 31;

    if (wid == 0) {
        asm volatile("tcgen05.alloc.cta_group::1.sync.aligned.shared::cta.b32 [%0], %1;"
                     :: "r"(sbase), "r"(256u) : "memory");
        asm volatile("tcgen05.relinquish_alloc_permit.cta_group::1.sync.aligned;");
    }
    if (tid == 0) {
#pragma unroll
        for (int s = 0; s < NSTAGE; ++s) {
            asm volatile("mbarrier.init.shared.b64 [%0], 1;"
                         :: "r"(sbase + 16 + s * 8) : "memory");   // full[s]
            asm volatile("mbarrier.init.shared.b64 [%0], 1;"
                         :: "r"(sbase + 40 + s * 8) : "memory");   // empty[s]
        }
    }
    __syncthreads();
    uint32_t tmem;
    asm volatile("ld.shared.b32 %0, [%1];" : "=r"(tmem) : "r"(sbase));

    if (tid == 0) {
        // 6 contiguous tile streams: A split0/1 (rowblk bm), B split0/1 x rowblk 2bn,2bn+1
        // B split tiles are ADJACENT in the stage => 256 contiguous N-rows per split.
        const char* srcs[6];
        srcs[0] = (const char*)(SPIKE ? g_as[br][0] : g_xms[0]) + (size_t)bm * 32 * TILEB;
        srcs[1] = (const char*)(SPIKE ? g_as[br][1] : g_xms[1]) + (size_t)bm * 32 * TILEB;
        const char* bw0 = (const char*)g_ws[SPIKE ? wsel : 3][0];
        const char* bw1 = (const char*)g_ws[SPIKE ? wsel : 3][1];
        srcs[2] = bw0 + (size_t)(bn * 2 + 0) * 32 * TILEB;
        srcs[3] = bw0 + (size_t)(bn * 2 + 1) * 32 * TILEB;
        srcs[4] = bw1 + (size_t)(bn * 2 + 0) * 32 * TILEB;
        srcs[5] = bw1 + (size_t)(bn * 2 + 1) * 32 * TILEB;

        // Prologue: chunks 0,1 -> stages 0,1.
#pragma unroll
        for (int s = 0; s < NSTAGE; ++s) {
            const uint32_t fb = sbase + 16 + s * 8;
            asm volatile("mbarrier.arrive.expect_tx.shared.b64 _, [%0], %1;"
                         :: "r"(fb), "r"((unsigned)STAGEB) : "memory");
#pragma unroll
            for (int ti = 0; ti < 6; ++ti)
                bulkcp(sbase + CTRLB + s * STAGEB + ti * TILEB,
                       srcs[ti] + (size_t)s * TILEB, fb);
        }

        int phF[NSTAGE] = {0, 0}, phE[NSTAGE] = {0, 0};
        const int PA[3] = {0, 0, 1};
        const int PB[3] = {0, 1, 0};

#pragma unroll 1
        for (int c = 0; c < NCHUNK; ++c) {
            const int s = c & 1;
            mbpoll(sbase + 16 + s * 8, phF[s]);
            phF[s] ^= 1;

            const uint32_t ab = sbase + CTRLB + (uint32_t)s * STAGEB;
#pragma unroll
            for (int p = 0; p < 3; ++p) {
                const uint64_t ad = mkdesc(ab + PA[p] * TILEB);
                const uint64_t bd = mkdesc(ab + (2 + PB[p] * 2) * TILEB);
#pragma unroll
                for (int ks = 0; ks < 4; ++ks) {
                    const uint32_t en = (c == 0 && p == 0 && ks == 0) ? 0u : 1u;
                    mma_ss(tmem, ad + ks * 2, bd + ks * 2, en);
                }
            }
            asm volatile(
                "tcgen05.commit.cta_group::1.mbarrier::arrive::one.shared::cluster.b64 [%0];"
                :: "r"(sbase + 40 + s * 8) : "memory");

            // After chunk c-1's MMAs complete, refill its stage with chunk c+1.
            if (c >= 1) {
                const int sp = (c - 1) & 1;
                mbpoll(sbase + 40 + sp * 8, phE[sp]);
                phE[sp] ^= 1;
                if (c + 1 < NCHUNK) {
                    const uint32_t fb = sbase + 16 + sp * 8;
                    asm volatile("mbarrier.arrive.expect_tx.shared.b64 _, [%0], %1;"
                                 :: "r"(fb), "r"((unsigned)STAGEB) : "memory");
                    const size_t q = (size_t)(c + 1) * TILEB;
#pragma unroll
                    for (int ti = 0; ti < 6; ++ti)
                        bulkcp(sbase + CTRLB + sp * STAGEB + ti * TILEB,
                               srcs[ti] + q, fb);
                }
            }
        }
        mbpoll(sbase + 40 + ((NCHUNK - 1) & 1) * 8, phE[(NCHUNK - 1) & 1]);
    }
    __syncthreads();
    asm volatile("tcgen05.fence::after_thread_sync;" ::: "memory");

    if (wid < 4) {
        const int row = bm * 128 + wid * 32 + lid;
#pragma unroll 1
        for (int cb = 0; cb < 256; cb += 32) {
            uint32_t rg[32];
            LDTM32(rg, tmem + cb);
            asm volatile("tcgen05.wait::ld.sync.aligned;" ::: "memory");
            if (SPIKE) {
                uint32_t pk[16];
#pragma unroll
                for (int jj = 0; jj < 16; ++jj) {
                    const int col0 = bn * 256 + cb + jj * 2;
                    const unsigned e0 =
                        ((unsigned)blockIdx.z << 22) | ((unsigned)row << 11) | (unsigned)col0;
                    const unsigned m0 = mask_or_flag(__uint_as_float(rg[jj * 2 + 0]), e0);
                    const unsigned m1 = mask_or_flag(__uint_as_float(rg[jj * 2 + 1]), e0 + 1);
                    pk[jj] = m0 | (m1 << 16);
                }
                uint4* dst = (uint4*)&g_masks[blockIdx.z][(size_t)row * CDIM + bn * 256 + cb];
#pragma unroll
                for (int q = 0; q < 4; ++q)
                    dst[q] = make_uint4(pk[q * 4], pk[q * 4 + 1], pk[q * 4 + 2], pk[q * 4 + 3]);
            } else {
                float4* dst = (float4*)&out[(size_t)row * CDIM + bn * 256 + cb];
#pragma unroll
                for (int q = 0; q < 8; ++q)
                    dst[q] = make_float4(__uint_as_float(rg[q * 4]),
                                         __uint_as_float(rg[q * 4 + 1]),
                                         __uint_as_float(rg[q * 4 + 2]),
                                         __uint_as_float(rg[q * 4 + 3]));
            }
        }
    }
    __syncthreads();
    if (tid == 0) {
#pragma unroll
        for (int s = 0; s < NSTAGE; ++s) {
            asm volatile("mbarrier.inval.shared.b64 [%0];" :: "r"(sbase + 16 + s * 8) : "memory");
            asm volatile("mbarrier.inval.shared.b64 [%0];" :: "r"(sbase + 40 + s * 8) : "memory");
        }
    }
    __syncthreads();
    if (wid == 0)
        asm volatile("tcgen05.dealloc.cta_group::1.sync.aligned.b32 %0, %1;"
                     :: "r"(tmem), "r"(256u));
#else
    // FFMA fallback (plain sm_103 pass): two 128-col halves sequentially.
    const __nv_bfloat16* pa[2] = {SPIKE ? g_as[br][0] : g_xms[0],
                                  SPIKE ? g_as[br][1] : g_xms[1]};
    const __nv_bfloat16* pb[2] = {g_ws[SPIKE ? wsel : 3][0], g_ws[SPIKE ? wsel : 3][1]};

    float (*As)[128] = (float (*)[128])smem;
    float (*Bs)[128] = (float (*)[128])(smem + 16 * 128 * 4);

    const int ty = tid >> 4, tx = tid & 15;
    const int aRow = tid >> 3, aCol = (tid & 7) * 2;
    const int bN = tid & 127, bKh = (tid >> 7) * 8;

    for (int nh2 = 0; nh2 < 2; ++nh2) {
        const int ncol = bn * 256 + nh2 * 128;
        float acc[8][8];
#pragma unroll
        for (int i = 0; i < 8; ++i)
#pragma unroll
            for (int j = 0; j < 8; ++j) acc[i][j] = 0.f;

        for (int kt = 0; kt < CDIM; kt += 16) {
            {
                float av[2] = {0.f, 0.f};
#pragma unroll
                for (int s = 0; s < 2; ++s)
#pragma unroll
                    for (int e = 0; e < 2; ++e)
                        av[e] += __bfloat162float(*(const __nv_bfloat16*)(
                            (const char*)pa[s] + tiled_off(bm * 128 + aRow, kt + aCol + e)));
#pragma unroll
                for (int e = 0; e < 2; ++e) As[aCol + e][aRow] = av[e];
            }
            {
#pragma unroll
                for (int e = 0; e < 8; ++e) {
                    float bv = 0.f;
#pragma unroll
                    for (int s = 0; s < 2; ++s)
                        bv += __bfloat162float(*(const __nv_bfloat16*)(
                            (const char*)pb[s] + tiled_off(ncol + bN, kt + bKh + e)));
                    Bs[bKh + e][bN] = bv;
                }
            }
            __syncthreads();

#pragma unroll
            for (int k = 0; k < 16; ++k) {
                float ra[8], rb[8];
#pragma unroll
                for (int i = 0; i < 8; ++i) ra[i] = As[k][ty * 8 + i];
#pragma unroll
                for (int j = 0; j < 8; ++j) rb[j] = Bs[k][tx * 8 + j];
#pragma unroll
                for (int i = 0; i < 8; ++i)
#pragma unroll
                    for (int j = 0; j < 8; ++j)
                        acc[i][j] = fmaf(ra[i], rb[j], acc[i][j]);
            }
            __syncthreads();
        }

        if (SPIKE) {
            unsigned short* Mo = g_masks[blockIdx.z];
#pragma unroll
            for (int i = 0; i < 8; ++i) {
                const int row = bm * 128 + ty * 8 + i;
#pragma unroll
                for (int j = 0; j < 8; ++j) {
                    const int col = ncol + tx * 8 + j;
                    const unsigned enc =
                        ((unsigned)blockIdx.z << 22) | ((unsigned)row << 11) | (unsigned)col;
                    Mo[(size_t)row * CDIM + col] =
                        (unsigned short)mask_or_flag(acc[i][j], enc);
                }
            }
        } else {
#pragma unroll
            for (int i = 0; i < 8; ++i) {
                const int row = bm * 128 + ty * 8 + i;
#pragma unroll
                for (int j = 0; j < 8; ++j)
                    out[(size_t)row * CDIM + ncol + tx * 8 + j] = acc[i][j];
            }
        }
        __syncthreads();
    }
#endif
}

// ---------------------------------------------------------------------------
// Repair: one thread per flagged element, strictly-sequential ascending-k
// fp32 fmaf chain (reference-exact summation order).
// ---------------------------------------------------------------------------
__global__ __launch_bounds__(256) void repair(const float* __restrict__ x) {
    const unsigned total = min(g_flagcnt, FLAG_CAP);
    for (unsigned e = blockIdx.x * 256 + threadIdx.x; e < total;
         e += gridDim.x * 256) {
        const unsigned enc = g_flags[e];
        const int z = enc >> 22;
        const int row = (enc >> 11) & 2047;
        const int col = enc & 2047;
        const int br = z / 3, ws = z % 3;
        const float4* xr = (const float4*)(x + (size_t)row * CDIM);
        const float4* wr = (const float4*)(g_wt[ws] + (size_t)col * CDIM);
        float acc = 0.f;
#pragma unroll 4
        for (int k4 = 0; k4 < CDIM / 4; ++k4) {
            const float4 a = xr[k4];
            const float4 b = wr[k4];
            float a0, a1, a2, a3;
            if (br) {
                a0 = fmaxf(-a.x, 0.f); a1 = fmaxf(-a.y, 0.f);
                a2 = fmaxf(-a.z, 0.f); a3 = fmaxf(-a.w, 0.f);
            } else {
                a0 = fmaxf(a.x, 0.f); a1 = fmaxf(a.y, 0.f);
                a2 = fmaxf(a.z, 0.f); a3 = fmaxf(a.w, 0.f);
            }
            acc = fmaf(a0, b.x, acc);
            acc = fmaf(a1, b.y, acc);
            acc = fmaf(a2, b.z, acc);
            acc = fmaf(a3, b.w, acc);
        }
        g_masks[z][(size_t)row * CDIM + col] = (unsigned short)if_scan_mask(acc);
    }
}

// ---------------------------------------------------------------------------
// Per-token spiking attention; writes Xm bf16 2-splits in tiled layout.
// ---------------------------------------------------------------------------
__global__ __launch_bounds__(256) void attn_k() {
    const int n = blockIdx.x;
    const int tid = threadIdx.x;

    __shared__ unsigned short Mp[3][CDIM];
    __shared__ unsigned short Mn[3][CDIM];
    __shared__ __align__(16) int8_t Qt[CDIM];
    __shared__ __align__(16) int8_t Kt[CDIM];
    __shared__ __align__(16) int8_t Vt[CDIM];
    __shared__ int attn_s[HEADS * HEADS];

    const size_t base = (size_t)n * CDIM;
    for (int c = tid; c < CDIM; c += 256) {
        Mp[0][c] = g_masks[0][base + c];
        Mp[1][c] = g_masks[1][base + c];
        Mp[2][c] = g_masks[2][base + c];
        Mn[0][c] = g_masks[3][base + c];
        Mn[1][c] = g_masks[4][base + c];
        Mn[2][c] = g_masks[5][base + c];
    }
    __syncthreads();

    int acc[8];
#pragma unroll
    for (int j = 0; j < 8; ++j) acc[j] = 0;

    const int h = tid >> 4;
    const int dbase = (tid & 15) * 8;

    for (int t = 0; t < TSTEPS; ++t) {
        for (int c = tid; c < CDIM; c += 256) {
            Qt[c] = (int8_t)(((Mp[0][c] >> t) & 1) - ((Mn[0][c] >> t) & 1));
            Kt[c] = (int8_t)(((Mp[1][c] >> t) & 1) - ((Mn[1][c] >> t) & 1));
            Vt[c] = (int8_t)(((Mp[2][c] >> t) & 1) - ((Mn[2][c] >> t) & 1));
        }
        __syncthreads();

        {
            const int hh = tid >> 4;
            const int mm = tid & 15;
            const int* qr = (const int*)(Qt + hh * 128);
            const int* kr = (const int*)(Kt + mm * 128);
            const int rot = (mm * 2) & 31;
            int s = 0;
#pragma unroll
            for (int w = 0; w < 32; ++w) {
                const int wi = (w + rot) & 31;
                s = __dp4a(qr[wi], kr[wi], s);
            }
            attn_s[hh * 16 + mm] = s;
        }
        __syncthreads();

#pragma unroll
        for (int m = 0; m < HEADS; ++m) {
            const int a = attn_s[h * 16 + m];
            const int8_t* vp = Vt + m * 128 + dbase;
#pragma unroll
            for (int j = 0; j < 8; ++j) acc[j] += a * (int)vp[j];
        }
        __syncthreads();
    }

#pragma unroll
    for (int j = 0; j < 8; ++j) {
        const float val = (float)acc[j] * 0.0125f;
        __nv_bfloat16 h0, h1;
        split2(val, h0, h1);
        const int c = (dbase + j) * HEADS + h;
        const size_t off = tiled_off(n, c);
        *(__nv_bfloat16*)((char*)g_xms[0] + off) = h0;
        *(__nv_bfloat16*)((char*)g_xms[1] + off) = h1;
    }
}

// ---------------------------------------------------------------------------
extern "C" void kernel_launch(void* const* d_in, const int* in_sizes, int n_in,
                              void* d_out, int out_size) {
    const float* x  = (const float*)d_in[0];
    const float* wq = (const float*)d_in[2];
    const float* wk = (const float*)d_in[3];
    const float* wv = (const float*)d_in[4];
    const float* wo = (const float*)d_in[5];
    float* out = (float*)d_out;

    cudaFuncSetAttribute(gemm_tc<true>, cudaFuncAttributeMaxDynamicSharedMemorySize,
                         SMEM_TOTAL);
    cudaFuncSetAttribute(gemm_tc<false>, cudaFuncAttributeMaxDynamicSharedMemorySize,
                         SMEM_TOTAL);

    reset_flags<<<1, 1>>>();
    prep_x<<<(NDIM * CDIM) / (256 * 4), 256>>>(x);
    prep_w<<<dim3(64, 64, 4), dim3(32, 8)>>>(wq, wk, wv, wo);
    gemm_tc<true><<<dim3(8, 16, 6), 256, SMEM_TOTAL>>>(nullptr);
    repair<<<1184, 256>>>(x);
    attn_k<<<NDIM, 256>>>();
    gemm_tc<false><<<dim3(8, 16, 1), 256, SMEM_TOTAL>>>(out);
}